// round 1
// baseline (speedup 1.0000x reference)
#include <cuda_runtime.h>

#define B_   128
#define S_   512
#define D_   256
#define H_   512
#define ODIM 1275

// ---------------- persistent device scratch ----------------
__device__ __align__(16) float g_xT[S_ * D_ * B_];        // [t][d][b]  64 MB
__device__ __align__(16) float g_W0p[128 * 768 * 16];     // [jtile][k][c], c = jj*4+gate
__device__ __align__(16) float g_W1p[128 * 1024 * 16];
__device__ __align__(16) float g_h0[2][H_ * B_];          // [buf][j][b]
__device__ __align__(16) float g_h1[2][H_ * B_];
__device__ unsigned g_bar_cnt = 0;
__device__ volatile unsigned g_bar_gen = 0;

// ---------------- grid-wide barrier (all CTAs resident) ----------------
__device__ __forceinline__ void grid_sync(unsigned G) {
    __syncthreads();
    if (threadIdx.x == 0) {
        __threadfence();
        unsigned gen = g_bar_gen;
        if (atomicAdd(&g_bar_cnt, 1u) == G - 1u) {
            g_bar_cnt = 0;
            __threadfence();
            g_bar_gen = gen + 1u;
        } else {
            while (g_bar_gen == gen) { }
            __threadfence();
        }
    }
    __syncthreads();
}

// ---------------- prep: transpose x, pack weights per jtile ----------------
__global__ void prep_kernel(const float* __restrict__ x,
                            const float* __restrict__ W0,
                            const float* __restrict__ W1)
{
    const int stride = gridDim.x * blockDim.x;
    const int tid0 = blockIdx.x * blockDim.x + threadIdx.x;

    // xT[t][d][b] = x[b][t][d]
    for (int idx = tid0; idx < S_ * D_ * B_; idx += stride) {
        int t = idx / (D_ * B_);
        int d = (idx / B_) % D_;
        int b = idx % B_;
        g_xT[idx] = x[(b * S_ + t) * D_ + d];
    }
    // W0p[jt][k][c], c = jj*4 + g  ->  W0[k][g*512 + jt*4 + jj]
    for (int idx = tid0; idx < 128 * 768 * 16; idx += stride) {
        int jt = idx / (768 * 16);
        int k  = (idx >> 4) % 768;
        int c  = idx & 15;
        g_W0p[idx] = W0[k * 2048 + (c & 3) * 512 + jt * 4 + (c >> 2)];
    }
    for (int idx = tid0; idx < 128 * 1024 * 16; idx += stride) {
        int jt = idx / (1024 * 16);
        int k  = (idx >> 4) % 1024;
        int c  = idx & 15;
        g_W1p[idx] = W1[k * 2048 + (c & 3) * 512 + jt * 4 + (c >> 2)];
    }
}

// ---------------- fused GEMM(+K-split reduce)+gate phase ----------------
// output cols per CTA: 16 = 4 jj * 4 gates. Threads: 512 = 4 ksplit * 32 btile * 4 ctile.
// Each thread: 4b x 4c register tile. act smem layout [k][b] (float4 over b),
// wt smem layout [k][16] (float4 over c). K-split partials reduced via smem (aliases act).
__device__ __forceinline__ void lstm_phase(
    const float4* __restrict__ srcA, int KA,      // rows [0,KA): float4 rows of 32
    const float4* __restrict__ srcB, bool bZero,  // rows [KA,K)
    const float4* __restrict__ wsrc,              // packed weights: row k -> 4 float4
    int K,
    const float* __restrict__ bias, int j0,
    float* cstate, float* hout,
    float4* s_act4, float4* s_wt4,
    int tid, int ks, int r, int bt, int ct)
{
    float4 a0 = make_float4(0,0,0,0), a1 = a0, a2 = a0, a3 = a0;
    const int nch = K >> 6;
    for (int ch = 0; ch < nch; ch++) {
        const int k0 = ch << 6;
        // stage activations: 64 rows x 128 floats, perfectly coalesced
        #pragma unroll
        for (int i = 0; i < 4; i++) {
            int idx = tid + (i << 9);
            int k = k0 + (idx >> 5);
            int bq = idx & 31;
            float4 v;
            if (k < KA)       v = srcA[k * 32 + bq];
            else if (bZero)   v = make_float4(0,0,0,0);
            else              v = srcB[(k - KA) * 32 + bq];
            s_act4[idx] = v;
        }
        // stage packed weights: 64 rows x 16 floats
        if (tid < 256) s_wt4[tid] = wsrc[((k0 + (tid >> 2)) << 2) + (tid & 3)];
        __syncthreads();
        #pragma unroll
        for (int u = 0; u < 16; u++) {
            int k = (u << 2) | ks;
            float4 a = s_act4[(k << 5) + bt];
            float4 w = s_wt4[(k << 2) + ct];
            a0.x += a.x * w.x; a0.y += a.x * w.y; a0.z += a.x * w.z; a0.w += a.x * w.w;
            a1.x += a.y * w.x; a1.y += a.y * w.y; a1.z += a.y * w.z; a1.w += a.y * w.w;
            a2.x += a.z * w.x; a2.y += a.z * w.y; a2.z += a.z * w.z; a2.w += a.z * w.w;
            a3.x += a.w * w.x; a3.y += a.w * w.y; a3.z += a.w * w.z; a3.w += a.w * w.w;
        }
        __syncthreads();
    }
    // ---- K-split reduction (smem aliases act buffer) ----
    if (ks > 0) {
        float4* p = s_act4 + ((((ks - 1) << 7) + r) << 2);
        p[0] = a0; p[1] = a1; p[2] = a2; p[3] = a3;
    }
    __syncthreads();
    if (ks == 0) {
        #pragma unroll
        for (int s2 = 0; s2 < 3; s2++) {
            const float4* p = s_act4 + (((s2 << 7) + r) << 2);
            float4 q;
            q = p[0]; a0.x += q.x; a0.y += q.y; a0.z += q.z; a0.w += q.w;
            q = p[1]; a1.x += q.x; a1.y += q.y; a1.z += q.z; a1.w += q.w;
            q = p[2]; a2.x += q.x; a2.y += q.y; a2.z += q.z; a2.w += q.w;
            q = p[3]; a3.x += q.x; a3.y += q.y; a3.z += q.z; a3.w += q.w;
        }
        // ---- gate update: component x/y/z/w of acc = gates i/f/g/o ----
        const int j = j0 + ct;
        const float bi = bias[j];
        const float bf = bias[H_ + j];
        const float bg = bias[2 * H_ + j];
        const float bo = bias[3 * H_ + j];
        float4 A[4] = {a0, a1, a2, a3};
        #pragma unroll
        for (int ib = 0; ib < 4; ib++) {
            int b = (bt << 2) + ib;
            float zi = A[ib].x + bi;
            float zf = A[ib].y + bf;
            float zg = A[ib].z + bg;
            float zo = A[ib].w + bo;
            float si = 1.f / (1.f + expf(-zi));
            float sf = 1.f / (1.f + expf(-zf));
            float tg = tanhf(zg);
            float so = 1.f / (1.f + expf(-zo));
            float cn = sf * cstate[(ct << 7) + b] + si * tg;
            cstate[(ct << 7) + b] = cn;
            hout[j * 128 + b] = so * tanhf(cn);
        }
    }
    __syncthreads();
}

// ---------------- persistent main kernel: 128 CTAs x 512 threads ----------------
__global__ void __launch_bounds__(512, 1)
lstm_main(const float* __restrict__ b0,
          const float* __restrict__ b1,
          const float* __restrict__ Wp,
          const float* __restrict__ bp,
          float* __restrict__ out)
{
    __shared__ __align__(16) float s_act[64 * 128];  // also K-split reduce buffer
    __shared__ __align__(16) float s_wt[64 * 16];
    __shared__ float s_c0[4 * 128];
    __shared__ float s_c1[4 * 128];

    const int tid = threadIdx.x;
    const unsigned G = gridDim.x;
    const int jt = blockIdx.x;   // 0..127: owns hidden cols [jt*4, jt*4+4)
    const int j0 = jt * 4;
    const int ks = tid >> 7;
    const int r  = tid & 127;
    const int bt = r >> 2;
    const int ct = r & 3;

    s_c0[tid] = 0.f;
    s_c1[tid] = 0.f;
    __syncthreads();

    float4* s_act4 = (float4*)s_act;
    float4* s_wt4  = (float4*)s_wt;

    const float4* W0p4 = (const float4*)g_W0p + (size_t)jt * 768 * 4;
    const float4* W1p4 = (const float4*)g_W1p + (size_t)jt * 1024 * 4;

    for (int t = 0; t < S_; t++) {
        const int cur = t & 1, prv = cur ^ 1;
        float* h0c = g_h0[cur];
        const float* h0p = g_h0[prv];
        float* h1c = g_h1[cur];
        const float* h1p = g_h1[prv];

        // L0: act = [x_t (256) | h0_prev (512)], K = 768
        lstm_phase((const float4*)g_xT + (size_t)t * (256 * 32), 256,
                   (const float4*)h0p, t == 0,
                   W0p4, 768, b0, j0, s_c0, h0c,
                   s_act4, s_wt4, tid, ks, r, bt, ct);

        grid_sync(G);   // h0(t) visible to all CTAs; also orders h1(t-1) WAR

        // L1: act = [h0_cur (512) | h1_prev (512)], K = 1024
        lstm_phase((const float4*)h0c, 512,
                   (const float4*)h1p, t == 0,
                   W1p4, 1024, b1, j0, s_c1, h1c,
                   s_act4, s_wt4, tid, ks, r, bt, ct);
        // no barrier needed here: next step's L0-barrier orders L1(t)->L1(t+1)
    }

    grid_sync(G);   // final h1 visible everywhere

    // ---- projection: out[b][m] = sum_k h1T[k][b] * Wp[k][m] + bp[m] ----
    {
        const float* h1f = g_h1[1];   // t = 511 -> cur = 1
        int mstart = jt * 10;
        int mend = mstart + 10; if (mend > ODIM) mend = ODIM;
        int b  = tid & 127;
        int mq = tid >> 7;
        for (int m = mstart + mq; m < mend; m += 4) {
            float acc = bp[m];
            #pragma unroll 4
            for (int k = 0; k < H_; k += 4) {
                acc += h1f[(k + 0) * 128 + b] * Wp[(k + 0) * ODIM + m];
                acc += h1f[(k + 1) * 128 + b] * Wp[(k + 1) * ODIM + m];
                acc += h1f[(k + 2) * 128 + b] * Wp[(k + 2) * ODIM + m];
                acc += h1f[(k + 3) * 128 + b] * Wp[(k + 3) * ODIM + m];
            }
            out[b * ODIM + m] = acc;
        }
    }
}

// ---------------- entry ----------------
extern "C" void kernel_launch(void* const* d_in, const int* in_sizes, int n_in,
                              void* d_out, int out_size)
{
    const float* x  = (const float*)d_in[0];
    const float* W0 = (const float*)d_in[1];
    const float* b0 = (const float*)d_in[2];
    const float* W1 = (const float*)d_in[3];
    const float* b1 = (const float*)d_in[4];
    const float* Wp = (const float*)d_in[5];
    const float* bp = (const float*)d_in[6];
    float* out = (float*)d_out;

    prep_kernel<<<2048, 256>>>(x, W0, W1);
    lstm_main<<<128, 512>>>(b0, b1, Wp, bp, out);
}

// round 2
// speedup vs baseline: 1.4695x; 1.4695x over previous
#include <cuda_runtime.h>

#define B_   128
#define S_   512
#define D_   256
#define H_   512
#define ODIM 1275

typedef unsigned long long u64;

// ---------------- persistent device scratch ----------------
__device__ __align__(16) float g_xT[S_ * D_ * B_];        // [t][d][b]
__device__ __align__(16) float g_W0p[128 * 768 * 16];     // [jtile][k][c], c = jj*4+gate
__device__ __align__(16) float g_W1p[128 * 1024 * 16];
__device__ __align__(16) float g_h0[2][H_ * B_];          // [buf][j][b]
__device__ __align__(16) float g_h1[2][H_ * B_];
__device__ unsigned g_bar_cnt = 0;
__device__ volatile unsigned g_bar_gen = 0;

// ---------------- f32x2 helpers ----------------
__device__ __forceinline__ u64 pk2(float x, float y) {
    u64 r; asm("mov.b64 %0, {%1, %2};" : "=l"(r) : "f"(x), "f"(y)); return r;
}
__device__ __forceinline__ float2 up2(u64 v) {
    float2 r; asm("mov.b64 {%0, %1}, %2;" : "=f"(r.x), "=f"(r.y) : "l"(v)); return r;
}
__device__ __forceinline__ u64 add2(u64 a, u64 b) {
    u64 r; asm("add.rn.f32x2 %0, %1, %2;" : "=l"(r) : "l"(a), "l"(b)); return r;
}
#define FMA2(acc, a, b) asm("fma.rn.f32x2 %0, %1, %2, %0;" : "+l"(acc) : "l"(a), "l"(b))

// ---------------- cp.async ----------------
__device__ __forceinline__ void cp16(float4* dst, const float4* src) {
    unsigned d = (unsigned)__cvta_generic_to_shared(dst);
    asm volatile("cp.async.cg.shared.global [%0], [%1], 16;\n" :: "r"(d), "l"(src));
}
__device__ __forceinline__ void cp_commit() { asm volatile("cp.async.commit_group;\n" ::); }
__device__ __forceinline__ void cp_wait0()  { asm volatile("cp.async.wait_group 0;\n" ::); }

// ---------------- grid-wide barrier (all CTAs resident) ----------------
__device__ __forceinline__ void grid_sync(unsigned G) {
    __syncthreads();
    if (threadIdx.x == 0) {
        __threadfence();
        unsigned gen = g_bar_gen;
        if (atomicAdd(&g_bar_cnt, 1u) == G - 1u) {
            g_bar_cnt = 0;
            __threadfence();
            g_bar_gen = gen + 1u;
        } else {
            while (g_bar_gen == gen) { }
            __threadfence();
        }
    }
    __syncthreads();
}

// ---------------- prep: transpose x, pack weights per jtile ----------------
__global__ void prep_kernel(const float* __restrict__ x,
                            const float* __restrict__ W0,
                            const float* __restrict__ W1)
{
    const int stride = gridDim.x * blockDim.x;
    const int tid0 = blockIdx.x * blockDim.x + threadIdx.x;

    for (int idx = tid0; idx < S_ * D_ * B_; idx += stride) {
        int t = idx / (D_ * B_);
        int d = (idx / B_) % D_;
        int b = idx % B_;
        g_xT[idx] = x[(b * S_ + t) * D_ + d];
    }
    for (int idx = tid0; idx < 128 * 768 * 16; idx += stride) {
        int jt = idx / (768 * 16);
        int k  = (idx >> 4) % 768;
        int c  = idx & 15;
        g_W0p[idx] = W0[k * 2048 + (c & 3) * 512 + jt * 4 + (c >> 2)];
    }
    for (int idx = tid0; idx < 128 * 1024 * 16; idx += stride) {
        int jt = idx / (1024 * 16);
        int k  = (idx >> 4) % 1024;
        int c  = idx & 15;
        g_W1p[idx] = W1[k * 2048 + (c & 3) * 512 + jt * 4 + (c >> 2)];
    }
}

// ---------------- activation chunk prefetch (64 k-rows x 128 b) ----------------
__device__ __forceinline__ void prefetch_chunk(
    float4* s_act4, const float4* srcA, const float4* srcB, bool zeroB,
    int ch, int xch, int tid)
{
    float4* dst = s_act4 + ((ch & 1) << 11);
    if (ch < xch) {
        const float4* s = srcA + ((size_t)ch << 11);
        #pragma unroll
        for (int i = 0; i < 8; i++) { int idx = tid + (i << 8); cp16(dst + idx, s + idx); }
    } else if (zeroB) {
        float4 zz = make_float4(0.f, 0.f, 0.f, 0.f);
        #pragma unroll
        for (int i = 0; i < 8; i++) { int idx = tid + (i << 8); dst[idx] = zz; }
    } else {
        const float4* s = srcB + ((size_t)(ch - xch) << 11);
        #pragma unroll
        for (int i = 0; i < 8; i++) { int idx = tid + (i << 8); cp16(dst + idx, s + idx); }
    }
}

// ---------------- fused GEMM (FFMA2, K-split 4) + gates ----------------
// 256 threads = 4 ksplit x (16 bt x 4 ct). Thread tile: 8 batches x 4 gates of
// hidden unit j0+ct. Acc: 16 u64 = acc[gate*4 + bpair].
__device__ __forceinline__ void do_phase(
    const float4* __restrict__ srcA, const float4* __restrict__ srcB, bool zeroB,
    int nch, int xch,
    const float4* __restrict__ s_w4,
    float4* s_act4, float* cstate, float* __restrict__ hout,
    const float* __restrict__ bias,
    int tid, int ks, int r, int bt, int ct, int j0)
{
    u64 acc[16];
    #pragma unroll
    for (int i = 0; i < 16; i++) acc[i] = 0ull;

    prefetch_chunk(s_act4, srcA, srcB, zeroB, 0, xch, tid);
    cp_commit();

    for (int ch = 0; ch < nch; ch++) {
        cp_wait0();
        __syncthreads();
        if (ch + 1 < nch) {
            prefetch_chunk(s_act4, srcA, srcB, zeroB, ch + 1, xch, tid);
            cp_commit();
        }
        const float4* ab = s_act4 + ((ch & 1) << 11);
        const int kbase = ch << 6;
        #pragma unroll
        for (int u = 0; u < 16; u++) {
            const int k = (u << 2) | ks;
            float4 a0q = ab[(k << 5) + (bt << 1)];
            float4 a1q = ab[(k << 5) + (bt << 1) + 1];
            float4 wq  = s_w4[((kbase + k) << 2) + ct];
            u64 p0 = pk2(a0q.x, a0q.y), p1 = pk2(a0q.z, a0q.w);
            u64 p2 = pk2(a1q.x, a1q.y), p3 = pk2(a1q.z, a1q.w);
            u64 s0 = pk2(wq.x, wq.x), s1 = pk2(wq.y, wq.y);
            u64 s2 = pk2(wq.z, wq.z), s3 = pk2(wq.w, wq.w);
            FMA2(acc[0],  p0, s0); FMA2(acc[1],  p1, s0); FMA2(acc[2],  p2, s0); FMA2(acc[3],  p3, s0);
            FMA2(acc[4],  p0, s1); FMA2(acc[5],  p1, s1); FMA2(acc[6],  p2, s1); FMA2(acc[7],  p3, s1);
            FMA2(acc[8],  p0, s2); FMA2(acc[9],  p1, s2); FMA2(acc[10], p2, s2); FMA2(acc[11], p3, s2);
            FMA2(acc[12], p0, s3); FMA2(acc[13], p1, s3); FMA2(acc[14], p2, s3); FMA2(acc[15], p3, s3);
        }
    }

    // ---- write K-split partials into act buffer 0 (free after last compute) ----
    {
        ulonglong2* pb = (ulonglong2*)s_act4;
        size_t base = (size_t)((ks << 6) + r) << 3;   // 8 ulonglong2 per row
        #pragma unroll
        for (int i = 0; i < 8; i++) pb[base + i] = make_ulonglong2(acc[2 * i], acc[2 * i + 1]);
    }
    __syncthreads();

    // ---- reduce across ksplit + gate math; thread -> (rq, pair p) = 2 batches, 1 j ----
    {
        const int rq  = tid & 63;
        const int p   = tid >> 6;
        const int btq = rq >> 2;
        const int ctq = rq & 3;
        const u64* rb = (const u64*)s_act4;

        u64 z[4];
        #pragma unroll
        for (int c = 0; c < 4; c++) {
            u64 s = rb[((size_t)rq << 4) + (c << 2) + p];
            #pragma unroll
            for (int kk = 1; kk < 4; kk++)
                s = add2(s, rb[(((size_t)(kk << 6) + rq) << 4) + (c << 2) + p]);
            z[c] = s;
        }
        const int j = j0 + ctq;
        const float bi = bias[j];
        const float bf = bias[H_ + j];
        const float bg = bias[2 * H_ + j];
        const float bo = bias[3 * H_ + j];
        float2 zi = up2(z[0]), zf = up2(z[1]), zg = up2(z[2]), zo = up2(z[3]);

        const int b0 = (btq << 3) + (p << 1);
        float* cs = cstate + ctq * 128 + b0;

        float siA = 1.f / (1.f + expf(-(zi.x + bi)));
        float sfA = 1.f / (1.f + expf(-(zf.x + bf)));
        float tgA = tanhf(zg.x + bg);
        float soA = 1.f / (1.f + expf(-(zo.x + bo)));
        float cnA = sfA * cs[0] + siA * tgA;
        cs[0] = cnA;
        float hA = soA * tanhf(cnA);

        float siB = 1.f / (1.f + expf(-(zi.y + bi)));
        float sfB = 1.f / (1.f + expf(-(zf.y + bf)));
        float tgB = tanhf(zg.y + bg);
        float soB = 1.f / (1.f + expf(-(zo.y + bo)));
        float cnB = sfB * cs[1] + siB * tgB;
        cs[1] = cnB;
        float hB = soB * tanhf(cnB);

        *(float2*)(hout + j * 128 + b0) = make_float2(hA, hB);
    }
    __syncthreads();
}

// ---------------- persistent main kernel: 128 CTAs x 256 threads ----------------
__global__ void __launch_bounds__(256, 1)
lstm_main(const float* __restrict__ b0g,
          const float* __restrict__ b1g,
          const float* __restrict__ Wp,
          const float* __restrict__ bp,
          float* __restrict__ out)
{
    extern __shared__ float smem[];
    float* s_w0  = smem;                    // 768*16   = 12288 floats
    float* s_w1  = s_w0 + 768 * 16;         // 1024*16  = 16384 floats
    float* s_act = s_w1 + 1024 * 16;        // 2*64*128 = 16384 floats
    float* s_c0  = s_act + 2 * 64 * 128;    // 512
    float* s_c1  = s_c0 + 512;              // 512

    const int tid = threadIdx.x;
    const unsigned G = gridDim.x;
    const int jt = blockIdx.x;
    const int j0 = jt * 4;
    const int ks = tid >> 6;
    const int r  = tid & 63;
    const int bt = r >> 2;
    const int ct = r & 3;

    // preload packed weights into smem (resident for entire kernel)
    {
        const float4* w0s = (const float4*)g_W0p + (size_t)jt * 768 * 4;
        const float4* w1s = (const float4*)g_W1p + (size_t)jt * 1024 * 4;
        float4* d0 = (float4*)s_w0;
        float4* d1 = (float4*)s_w1;
        for (int i = tid; i < 768 * 4; i += 256) d0[i] = w0s[i];
        for (int i = tid; i < 1024 * 4; i += 256) d1[i] = w1s[i];
    }
    for (int i = tid; i < 512; i += 256) { s_c0[i] = 0.f; s_c1[i] = 0.f; }
    __syncthreads();

    float4* s_act4 = (float4*)s_act;
    const float4* s_w04 = (const float4*)s_w0;
    const float4* s_w14 = (const float4*)s_w1;

    for (int t = 0; t < S_; t++) {
        const int cur = t & 1, prv = cur ^ 1;

        // L0: act = [x_t (256 rows) | h0_prev (512 rows)], 12 chunks (4 from x)
        do_phase((const float4*)(g_xT + (size_t)t * D_ * B_),
                 (const float4*)g_h0[prv], t == 0, 12, 4,
                 s_w04, s_act4, s_c0, g_h0[cur], b0g,
                 tid, ks, r, bt, ct, j0);

        grid_sync(G);   // h0(t) visible to all CTAs

        // L1: act = [h0_cur (512) | h1_prev (512)], 16 chunks (8 from h0)
        do_phase((const float4*)g_h0[cur],
                 (const float4*)g_h1[prv], t == 0, 16, 8,
                 s_w14, s_act4, s_c1, g_h1[cur], b1g,
                 tid, ks, r, bt, ct, j0);
        // next step's L0 grid_sync orders L1(t) -> L1(t+1)
    }

    grid_sync(G);

    // ---- projection: out[b][m] = sum_k h1T[k][b] * Wp[k][m] + bp[m] ----
    {
        const float* h1f = g_h1[1];   // t = 511 -> cur = 1
        int mstart = jt * 10;
        int mend = mstart + 10; if (mend > ODIM) mend = ODIM;
        int b  = tid & 127;
        int mq = tid >> 7;
        for (int m = mstart + mq; m < mend; m += 2) {
            float acc = bp[m];
            #pragma unroll 4
            for (int k = 0; k < H_; k += 4) {
                acc += h1f[(k + 0) * 128 + b] * Wp[(k + 0) * ODIM + m];
                acc += h1f[(k + 1) * 128 + b] * Wp[(k + 1) * ODIM + m];
                acc += h1f[(k + 2) * 128 + b] * Wp[(k + 2) * ODIM + m];
                acc += h1f[(k + 3) * 128 + b] * Wp[(k + 3) * ODIM + m];
            }
            out[b * ODIM + m] = acc;
        }
    }
}

// ---------------- entry ----------------
extern "C" void kernel_launch(void* const* d_in, const int* in_sizes, int n_in,
                              void* d_out, int out_size)
{
    const float* x  = (const float*)d_in[0];
    const float* W0 = (const float*)d_in[1];
    const float* b0 = (const float*)d_in[2];
    const float* W1 = (const float*)d_in[3];
    const float* b1 = (const float*)d_in[4];
    const float* Wp = (const float*)d_in[5];
    const float* bp = (const float*)d_in[6];
    float* out = (float*)d_out;

    cudaFuncSetAttribute(lstm_main, cudaFuncAttributeMaxDynamicSharedMemorySize, 184320);

    prep_kernel<<<2048, 256>>>(x, W0, W1);
    lstm_main<<<128, 256, 184320>>>(b0, b1, Wp, bp, out);
}